// round 6
// baseline (speedup 1.0000x reference)
#include <cuda_runtime.h>
#include <math.h>

// ---------------- problem constants (fixed by the dataset) ----------------
#define NMEAS   5120        // n
#define NTOT    16384       // N
#define BATCH   500
#define LDP     512         // padded batch leading dim for scratch
#define LSEC    512         // number of sections
#define MSEC    32          // section size
#define SIGMA2  0.2f
#define SCALE_C 3.1622776601683795f   // sqrt(n*P/L) = sqrt(10)
#define MAXITR  4

// ---------------- scratch (static device memory; no allocations) ----------
__device__ float g_y[(size_t)NMEAS * LDP];       // y = A x + noise
__device__ float g_t[(size_t)NMEAS * LDP];       // residual
__device__ float g_s[(size_t)NTOT  * LDP];       // current estimate (padded)
__device__ float g_r[(size_t)NTOT  * LDP];       // r = s + g W t
__device__ float g_taa;                          // sum(A*A) == sum(W*W)
__device__ float g_part[1024];                   // taa partials
__device__ float g_colpart[10 * LDP];            // per-row-chunk column partials of ||t||^2
__device__ float g_tau2[LDP];                    // per-batch tau^2

// ---------------- init: s_cur = s_in padded to LDP -------------------------
__global__ void init_s_kernel(const float* __restrict__ s_in) {
    size_t idx = (size_t)blockIdx.x * blockDim.x + threadIdx.x;   // over NTOT*LDP
    if (idx >= (size_t)NTOT * LDP) return;
    int j = (int)(idx >> 9);
    int b = (int)(idx & 511);
    g_s[idx] = (b < BATCH) ? s_in[(size_t)j * BATCH + b] : 0.0f;
}

// ---------------- taa = sum(A*A), deterministic two-pass -------------------
__global__ void taa_partial_kernel(const float* __restrict__ A) {
    const size_t n4 = (size_t)NMEAS * NTOT / 4;
    float s = 0.0f;
    for (size_t i = (size_t)blockIdx.x * blockDim.x + threadIdx.x; i < n4;
         i += (size_t)gridDim.x * blockDim.x) {
        float4 v = ((const float4*)A)[i];
        s += v.x * v.x + v.y * v.y + v.z * v.z + v.w * v.w;
    }
    __shared__ float sh[256];
    sh[threadIdx.x] = s;
    __syncthreads();
    for (int o = 128; o > 0; o >>= 1) {
        if (threadIdx.x < o) sh[threadIdx.x] += sh[threadIdx.x + o];
        __syncthreads();
    }
    if (threadIdx.x == 0) g_part[blockIdx.x] = sh[0];
}

__global__ void taa_final_kernel() {
    __shared__ float sh[1024];
    sh[threadIdx.x] = g_part[threadIdx.x];
    __syncthreads();
    for (int o = 512; o > 0; o >>= 1) {
        if (threadIdx.x < o) sh[threadIdx.x] += sh[threadIdx.x + o];
        __syncthreads();
    }
    if (threadIdx.x == 0) g_taa = sh[0];
}

// ---------------- GEMM: C[M,nc] = epilogue(A[M,K] * B[K,nc]) ---------------
// MODE 0: C = acc + E            (y = A x + noise)
// MODE 1: C = E - acc            (t = y - A s)
// MODE 2: C = E + gamma[gi]*acc  (r = s + g * W t)
// BM=BN=64, BK=16, 256 threads, 4x4 micro-tile per thread.
template <int MODE>
__global__ __launch_bounds__(256) void gemm64_kernel(
    const float* __restrict__ Aop, int lda,
    const float* __restrict__ Bop, int ldb,
    float*       __restrict__ Cop, int ldc,
    const float* __restrict__ Eop, int lde,
    const float* __restrict__ gamma, int gi,
    int K, int ncols)
{
    const int BK = 16;
    __shared__ float As[BK][64];   // transposed: As[k][m]
    __shared__ float Bs[BK][64];   // Bs[k][nb]

    const int tid = threadIdx.x;
    const int bm0 = blockIdx.y * 64;
    const int bn0 = blockIdx.x * 64;
    const int tx = tid & 15;       // 0..15 -> col group
    const int ty = tid >> 4;       // 0..15 -> row group
    const int ar = tid >> 2;       // 0..63  (A tile row)
    const int ac = (tid & 3) * 4;  // 0,4,8,12 (A tile k offset)
    const int br = tid >> 4;       // 0..15  (B tile k row)
    const int bc = (tid & 15) * 4; // 0..60  (B tile col offset)

    const float* Aptr = Aop + (size_t)(bm0 + ar) * lda + ac;
    const bool bfull = (bn0 + bc + 3) < ncols;

    float acc[4][4];
#pragma unroll
    for (int i = 0; i < 4; i++)
#pragma unroll
        for (int j = 0; j < 4; j++) acc[i][j] = 0.0f;

    for (int k0 = 0; k0 < K; k0 += BK) {
        // load A tile (64x16), store transposed
        float4 a = *(const float4*)(Aptr + k0);
        As[ac + 0][ar] = a.x;
        As[ac + 1][ar] = a.y;
        As[ac + 2][ar] = a.z;
        As[ac + 3][ar] = a.w;
        // load B tile (16x64)
        const float* Bp = Bop + (size_t)(k0 + br) * ldb + bn0 + bc;
        float4 b;
        if (bfull) {
            b = *(const float4*)Bp;
        } else {
            b.x = (bn0 + bc + 0 < ncols) ? Bp[0] : 0.0f;
            b.y = (bn0 + bc + 1 < ncols) ? Bp[1] : 0.0f;
            b.z = (bn0 + bc + 2 < ncols) ? Bp[2] : 0.0f;
            b.w = (bn0 + bc + 3 < ncols) ? Bp[3] : 0.0f;
        }
        *(float4*)&Bs[br][bc] = b;
        __syncthreads();

#pragma unroll
        for (int k = 0; k < BK; k++) {
            float4 av = *(const float4*)&As[k][ty * 4];
            float4 bv = *(const float4*)&Bs[k][tx * 4];
            float aa[4] = {av.x, av.y, av.z, av.w};
            float bb[4] = {bv.x, bv.y, bv.z, bv.w};
#pragma unroll
            for (int i = 0; i < 4; i++)
#pragma unroll
                for (int j = 0; j < 4; j++) acc[i][j] = fmaf(aa[i], bb[j], acc[i][j]);
        }
        __syncthreads();
    }

    float g = 0.0f;
    if (MODE == 2) g = gamma[gi];

#pragma unroll
    for (int i = 0; i < 4; i++) {
        const int m = bm0 + ty * 4 + i;
#pragma unroll
        for (int j = 0; j < 4; j++) {
            const int nb = bn0 + tx * 4 + j;
            if (nb < ncols) {
                const float e = Eop[(size_t)m * lde + nb];
                float o;
                if (MODE == 0)      o = acc[i][j] + e;
                else if (MODE == 1) o = e - acc[i][j];
                else                o = e + g * acc[i][j];
                Cop[(size_t)m * ldc + nb] = o;
            }
        }
    }
}

// ---------------- column ||t||^2 partials, deterministic -------------------
// grid (8 col-tiles of 64, 10 row-chunks of 512), 256 threads = 64 cols x 4 lanes
__global__ void col_partial_kernel() {
    const int c    = blockIdx.x * 64 + (threadIdx.x & 63);
    const int lane = threadIdx.x >> 6;     // 0..3
    const int r0   = blockIdx.y * 512;
    float s = 0.0f;
    for (int i = lane; i < 512; i += 4) {
        float v = g_t[(size_t)(r0 + i) * LDP + c];
        s += v * v;
    }
    __shared__ float sh[4][64];
    sh[lane][threadIdx.x & 63] = s;
    __syncthreads();
    if (lane == 0) {
        int cc = threadIdx.x & 63;
        g_colpart[(size_t)blockIdx.y * LDP + c] =
            sh[0][cc] + sh[1][cc] + sh[2][cc] + sh[3][cc];
    }
}

// ---------------- tau2 per batch column ------------------------------------
__global__ void tau2_kernel(const float* __restrict__ gamma, int gi) {
    const int c = threadIdx.x;   // 0..511
    float cs = 0.0f;
#pragma unroll
    for (int j = 0; j < 10; j++) cs += g_colpart[(size_t)j * LDP + c];
    const float taa = g_taa;
    const float v2  = (cs - (float)MSEC * SIGMA2) / taa;
    const float g   = gamma[gi];
    const float Nf  = (float)NTOT;
    const float tau2 = v2 / Nf * (Nf + (g * g - 2.0f * g) * (float)MSEC)
                     + g * g * taa * SIGMA2 / Nf;   // tww == taa (W = A^T)
    g_tau2[c] = tau2;
}

// ---------------- shrink: per-section softmax ------------------------------
// grid (4 col-chunks of 128, 512 sections), 128 threads
__global__ void shrink_kernel(float* __restrict__ out, int ldo) {
    const int c = blockIdx.x * 128 + threadIdx.x;
    if (c >= BATCH) return;
    const int l = blockIdx.y;
    const float inv = SCALE_C / g_tau2[c];
    float v[MSEC];
    float mx = -1e30f;
#pragma unroll
    for (int m = 0; m < MSEC; m++) {
        v[m] = g_r[(size_t)(l * MSEC + m) * LDP + c] * inv;
        mx = fmaxf(mx, v[m]);
    }
    float sum = 0.0f;
#pragma unroll
    for (int m = 0; m < MSEC; m++) {
        v[m] = expf(v[m] - mx);
        sum += v[m];
    }
    const float is = 1.0f / sum;
#pragma unroll
    for (int m = 0; m < MSEC; m++) {
        out[(size_t)(l * MSEC + m) * ldo + c] = v[m] * is;
    }
}

// ---------------- host driver ----------------------------------------------
extern "C" void kernel_launch(void* const* d_in, const int* in_sizes, int n_in,
                              void* d_out, int out_size) {
    const float* x     = (const float*)d_in[0];   // [N, B]
    const float* s_in  = (const float*)d_in[1];   // [N, B]
    const float* noise = (const float*)d_in[2];   // [n, B]
    const float* A     = (const float*)d_in[3];   // [n, N]
    const float* W     = (const float*)d_in[4];   // [N, n] (== A^T)
    const float* gamma = (const float*)d_in[5];   // [4]
    float* out = (float*)d_out;                   // [N, B]
    (void)in_sizes; (void)n_in; (void)out_size;   // max_itr (d_in[6]) fixed = 4

    float *yb, *tb, *sb, *rb;
    cudaGetSymbolAddress((void**)&yb, g_y);
    cudaGetSymbolAddress((void**)&tb, g_t);
    cudaGetSymbolAddress((void**)&sb, g_s);
    cudaGetSymbolAddress((void**)&rb, g_r);

    // s_cur = pad(s_in)
    {
        size_t total = (size_t)NTOT * LDP;
        init_s_kernel<<<(unsigned)((total + 255) / 256), 256>>>(s_in);
    }
    // taa
    taa_partial_kernel<<<1024, 256>>>(A);
    taa_final_kernel<<<1, 1024>>>();

    // y = A x + noise
    gemm64_kernel<0><<<dim3(8, NMEAS / 64), 256>>>(
        A, NTOT, x, BATCH, yb, LDP, noise, BATCH, nullptr, 0, NTOT, BATCH);

    for (int i = 0; i < MAXITR; i++) {
        // t = y - A s
        gemm64_kernel<1><<<dim3(8, NMEAS / 64), 256>>>(
            A, NTOT, sb, LDP, tb, LDP, yb, LDP, nullptr, 0, NTOT, BATCH);
        // tau2 from ||t||^2 columns
        col_partial_kernel<<<dim3(8, 10), 256>>>();
        tau2_kernel<<<1, 512>>>(gamma, i);
        // r = s + gamma[i] * (W t)
        gemm64_kernel<2><<<dim3(8, NTOT / 64), 256>>>(
            W, NMEAS, tb, LDP, rb, LDP, sb, LDP, gamma, i, NMEAS, BATCH);
        // s = shrink(r, tau2)
        if (i == MAXITR - 1)
            shrink_kernel<<<dim3(4, LSEC), 128>>>(out, BATCH);
        else
            shrink_kernel<<<dim3(4, LSEC), 128>>>(sb, LDP);
    }
}

// round 7
// speedup vs baseline: 1.0031x; 1.0031x over previous
#include <cuda_runtime.h>
#include <math.h>

// ---------------- problem constants (fixed by the dataset) ----------------
#define NMEAS   5120        // n
#define NTOT    16384       // N
#define BATCH   500
#define LDP     512         // padded batch leading dim for scratch
#define LSEC    512         // number of sections
#define MSEC    32          // section size
#define SIGMA2  0.2f
#define SCALE_C 3.1622776601683795f   // sqrt(n*P/L) = sqrt(10)
#define MAXITR  4

// ---------------- scratch (static device memory; no allocations) ----------
__device__ float g_y[(size_t)NMEAS * LDP];       // y = A x + noise
__device__ float g_t[(size_t)NMEAS * LDP];       // residual
__device__ float g_s[(size_t)NTOT  * LDP];       // current estimate (padded)
__device__ float g_r[(size_t)NTOT  * LDP];       // r = s + g W t
__device__ float g_taa;                          // sum(A*A) == sum(W*W)
__device__ float g_part[1024];                   // taa partials
__device__ float g_colpart[10 * LDP];            // per-row-chunk column partials of ||t||^2
__device__ float g_tau2[LDP];                    // per-batch tau^2

// ---------------- init: s_cur = s_in padded to LDP -------------------------
__global__ void init_s_kernel(const float* __restrict__ s_in) {
    size_t idx = (size_t)blockIdx.x * blockDim.x + threadIdx.x;   // over NTOT*LDP
    if (idx >= (size_t)NTOT * LDP) return;
    int j = (int)(idx >> 9);
    int b = (int)(idx & 511);
    g_s[idx] = (b < BATCH) ? s_in[(size_t)j * BATCH + b] : 0.0f;
}

// ---------------- taa = sum(A*A), deterministic two-pass -------------------
__global__ void taa_partial_kernel(const float* __restrict__ A) {
    const size_t n4 = (size_t)NMEAS * NTOT / 4;
    float s = 0.0f;
    for (size_t i = (size_t)blockIdx.x * blockDim.x + threadIdx.x; i < n4;
         i += (size_t)gridDim.x * blockDim.x) {
        float4 v = ((const float4*)A)[i];
        s += v.x * v.x + v.y * v.y + v.z * v.z + v.w * v.w;
    }
    __shared__ float sh[256];
    sh[threadIdx.x] = s;
    __syncthreads();
    for (int o = 128; o > 0; o >>= 1) {
        if (threadIdx.x < o) sh[threadIdx.x] += sh[threadIdx.x + o];
        __syncthreads();
    }
    if (threadIdx.x == 0) g_part[blockIdx.x] = sh[0];
}

__global__ void taa_final_kernel() {
    __shared__ float sh[1024];
    sh[threadIdx.x] = g_part[threadIdx.x];
    __syncthreads();
    for (int o = 512; o > 0; o >>= 1) {
        if (threadIdx.x < o) sh[threadIdx.x] += sh[threadIdx.x + o];
        __syncthreads();
    }
    if (threadIdx.x == 0) g_taa = sh[0];
}

// ---------------- GEMM: C[M,nc] = epilogue(A[M,K] * B[K,nc]) ---------------
// MODE 0: C = acc + E            (y = A x + noise)
// MODE 1: C = E - acc            (t = y - A s)
// MODE 2: C = E + gamma[gi]*acc  (r = s + g * W t)
// BM=BN=64, BK=16, 256 threads, 4x4 micro-tile per thread.
template <int MODE>
__global__ __launch_bounds__(256) void gemm64_kernel(
    const float* __restrict__ Aop, int lda,
    const float* __restrict__ Bop, int ldb,
    float*       __restrict__ Cop, int ldc,
    const float* __restrict__ Eop, int lde,
    const float* __restrict__ gamma, int gi,
    int K, int ncols)
{
    const int BK = 16;
    __shared__ float As[BK][64];   // transposed: As[k][m]
    __shared__ float Bs[BK][64];   // Bs[k][nb]

    const int tid = threadIdx.x;
    const int bm0 = blockIdx.y * 64;
    const int bn0 = blockIdx.x * 64;
    const int tx = tid & 15;       // 0..15 -> col group
    const int ty = tid >> 4;       // 0..15 -> row group
    const int ar = tid >> 2;       // 0..63  (A tile row)
    const int ac = (tid & 3) * 4;  // 0,4,8,12 (A tile k offset)
    const int br = tid >> 4;       // 0..15  (B tile k row)
    const int bc = (tid & 15) * 4; // 0..60  (B tile col offset)

    const float* Aptr = Aop + (size_t)(bm0 + ar) * lda + ac;
    const bool bfull = (bn0 + bc + 3) < ncols;

    float acc[4][4];
#pragma unroll
    for (int i = 0; i < 4; i++)
#pragma unroll
        for (int j = 0; j < 4; j++) acc[i][j] = 0.0f;

    for (int k0 = 0; k0 < K; k0 += BK) {
        // load A tile (64x16), store transposed
        float4 a = *(const float4*)(Aptr + k0);
        As[ac + 0][ar] = a.x;
        As[ac + 1][ar] = a.y;
        As[ac + 2][ar] = a.z;
        As[ac + 3][ar] = a.w;
        // load B tile (16x64)
        const float* Bp = Bop + (size_t)(k0 + br) * ldb + bn0 + bc;
        float4 b;
        if (bfull) {
            b = *(const float4*)Bp;
        } else {
            b.x = (bn0 + bc + 0 < ncols) ? Bp[0] : 0.0f;
            b.y = (bn0 + bc + 1 < ncols) ? Bp[1] : 0.0f;
            b.z = (bn0 + bc + 2 < ncols) ? Bp[2] : 0.0f;
            b.w = (bn0 + bc + 3 < ncols) ? Bp[3] : 0.0f;
        }
        *(float4*)&Bs[br][bc] = b;
        __syncthreads();

#pragma unroll
        for (int k = 0; k < BK; k++) {
            float4 av = *(const float4*)&As[k][ty * 4];
            float4 bv = *(const float4*)&Bs[k][tx * 4];
            float aa[4] = {av.x, av.y, av.z, av.w};
            float bb[4] = {bv.x, bv.y, bv.z, bv.w};
#pragma unroll
            for (int i = 0; i < 4; i++)
#pragma unroll
                for (int j = 0; j < 4; j++) acc[i][j] = fmaf(aa[i], bb[j], acc[i][j]);
        }
        __syncthreads();
    }

    float g = 0.0f;
    if (MODE == 2) g = gamma[gi];

#pragma unroll
    for (int i = 0; i < 4; i++) {
        const int m = bm0 + ty * 4 + i;
#pragma unroll
        for (int j = 0; j < 4; j++) {
            const int nb = bn0 + tx * 4 + j;
            if (nb < ncols) {
                const float e = Eop[(size_t)m * lde + nb];
                float o;
                if (MODE == 0)      o = acc[i][j] + e;
                else if (MODE == 1) o = e - acc[i][j];
                else                o = e + g * acc[i][j];
                Cop[(size_t)m * ldc + nb] = o;
            }
        }
    }
}

// ---------------- column ||t||^2 partials, deterministic -------------------
// grid (8 col-tiles of 64, 10 row-chunks of 512), 256 threads = 64 cols x 4 lanes
__global__ void col_partial_kernel() {
    const int c    = blockIdx.x * 64 + (threadIdx.x & 63);
    const int lane = threadIdx.x >> 6;     // 0..3
    const int r0   = blockIdx.y * 512;
    float s = 0.0f;
    for (int i = lane; i < 512; i += 4) {
        float v = g_t[(size_t)(r0 + i) * LDP + c];
        s += v * v;
    }
    __shared__ float sh[4][64];
    sh[lane][threadIdx.x & 63] = s;
    __syncthreads();
    if (lane == 0) {
        int cc = threadIdx.x & 63;
        g_colpart[(size_t)blockIdx.y * LDP + c] =
            sh[0][cc] + sh[1][cc] + sh[2][cc] + sh[3][cc];
    }
}

// ---------------- tau2 per batch column ------------------------------------
__global__ void tau2_kernel(const float* __restrict__ gamma, int gi) {
    const int c = threadIdx.x;   // 0..511
    float cs = 0.0f;
#pragma unroll
    for (int j = 0; j < 10; j++) cs += g_colpart[(size_t)j * LDP + c];
    const float taa = g_taa;
    const float v2  = (cs - (float)MSEC * SIGMA2) / taa;
    const float g   = gamma[gi];
    const float Nf  = (float)NTOT;
    const float tau2 = v2 / Nf * (Nf + (g * g - 2.0f * g) * (float)MSEC)
                     + g * g * taa * SIGMA2 / Nf;   // tww == taa (W = A^T)
    g_tau2[c] = tau2;
}

// ---------------- shrink: per-section softmax ------------------------------
// grid (4 col-chunks of 128, 512 sections), 128 threads
__global__ void shrink_kernel(float* __restrict__ out, int ldo) {
    const int c = blockIdx.x * 128 + threadIdx.x;
    if (c >= BATCH) return;
    const int l = blockIdx.y;
    const float inv = SCALE_C / g_tau2[c];
    float v[MSEC];
    float mx = -1e30f;
#pragma unroll
    for (int m = 0; m < MSEC; m++) {
        v[m] = g_r[(size_t)(l * MSEC + m) * LDP + c] * inv;
        mx = fmaxf(mx, v[m]);
    }
    float sum = 0.0f;
#pragma unroll
    for (int m = 0; m < MSEC; m++) {
        v[m] = expf(v[m] - mx);
        sum += v[m];
    }
    const float is = 1.0f / sum;
#pragma unroll
    for (int m = 0; m < MSEC; m++) {
        out[(size_t)(l * MSEC + m) * ldo + c] = v[m] * is;
    }
}

// ---------------- host driver ----------------------------------------------
extern "C" void kernel_launch(void* const* d_in, const int* in_sizes, int n_in,
                              void* d_out, int out_size) {
    const float* x     = (const float*)d_in[0];   // [N, B]
    const float* s_in  = (const float*)d_in[1];   // [N, B]
    const float* noise = (const float*)d_in[2];   // [n, B]
    const float* A     = (const float*)d_in[3];   // [n, N]
    const float* W     = (const float*)d_in[4];   // [N, n] (== A^T)
    const float* gamma = (const float*)d_in[5];   // [4]
    float* out = (float*)d_out;                   // [N, B]
    (void)in_sizes; (void)n_in; (void)out_size;   // max_itr (d_in[6]) fixed = 4

    float *yb, *tb, *sb, *rb;
    cudaGetSymbolAddress((void**)&yb, g_y);
    cudaGetSymbolAddress((void**)&tb, g_t);
    cudaGetSymbolAddress((void**)&sb, g_s);
    cudaGetSymbolAddress((void**)&rb, g_r);

    // s_cur = pad(s_in)
    {
        size_t total = (size_t)NTOT * LDP;
        init_s_kernel<<<(unsigned)((total + 255) / 256), 256>>>(s_in);
    }
    // taa
    taa_partial_kernel<<<1024, 256>>>(A);
    taa_final_kernel<<<1, 1024>>>();

    // y = A x + noise
    gemm64_kernel<0><<<dim3(8, NMEAS / 64), 256>>>(
        A, NTOT, x, BATCH, yb, LDP, noise, BATCH, nullptr, 0, NTOT, BATCH);

    for (int i = 0; i < MAXITR; i++) {
        // t = y - A s
        gemm64_kernel<1><<<dim3(8, NMEAS / 64), 256>>>(
            A, NTOT, sb, LDP, tb, LDP, yb, LDP, nullptr, 0, NTOT, BATCH);
        // tau2 from ||t||^2 columns
        col_partial_kernel<<<dim3(8, 10), 256>>>();
        tau2_kernel<<<1, 512>>>(gamma, i);
        // r = s + gamma[i] * (W t)
        gemm64_kernel<2><<<dim3(8, NTOT / 64), 256>>>(
            W, NMEAS, tb, LDP, rb, LDP, sb, LDP, gamma, i, NMEAS, BATCH);
        // s = shrink(r, tau2)
        if (i == MAXITR - 1)
            shrink_kernel<<<dim3(4, LSEC), 128>>>(out, BATCH);
        else
            shrink_kernel<<<dim3(4, LSEC), 128>>>(sb, LDP);
    }
}